// round 1
// baseline (speedup 1.0000x reference)
#include <cuda_runtime.h>
#include <cuda_bf16.h>
#include <math.h>

// Problem constants
#define BB   2
#define SS   2048
#define DD   1024
#define HH   16
#define DKK  64
#define DFFF 4096
#define MM   (BB * SS)          // 4096 rows
#define EPSF 1.1920929e-07f     // np.finfo(np.float32).eps

// ---------------------------------------------------------------------------
// Scratch (device globals — no cudaMalloc allowed)
// ---------------------------------------------------------------------------
__device__ float g_h  [MM * DD];    // rmsnorm1 output
__device__ float g_q  [MM * DD];
__device__ float g_k  [MM * DD];
__device__ float g_v  [MM * DD];
__device__ float g_o  [MM * DD];    // attention output (b,s,h,dk) flattened
__device__ float g_x2 [MM * DD];    // x + attn_out
__device__ float g_h2 [MM * DD];    // rmsnorm2 output
__device__ float g_ff [MM * DFFF];  // relu(h2@w1+b1)

// ---------------------------------------------------------------------------
// RMSNorm: one block per row (D=1024), 256 threads, each owns one float4
// ---------------------------------------------------------------------------
__global__ void __launch_bounds__(256) rmsnorm_kernel(
    const float* __restrict__ x, const float* __restrict__ g,
    float* __restrict__ out)
{
    int row = blockIdx.x;
    const float4* xr = (const float4*)(x + (size_t)row * DD);
    float4 xv = xr[threadIdx.x];
    float ss = xv.x * xv.x + xv.y * xv.y + xv.z * xv.z + xv.w * xv.w;

    // warp reduce
    #pragma unroll
    for (int off = 16; off > 0; off >>= 1)
        ss += __shfl_xor_sync(0xFFFFFFFFu, ss, off);

    __shared__ float sred[8];
    __shared__ float sscale;
    int warp = threadIdx.x >> 5;
    if ((threadIdx.x & 31) == 0) sred[warp] = ss;
    __syncthreads();
    if (threadIdx.x == 0) {
        float t = 0.f;
        #pragma unroll
        for (int i = 0; i < 8; i++) t += sred[i];
        sscale = rsqrtf(t / (float)DD + EPSF);
    }
    __syncthreads();
    float sc = sscale;

    float4 gv = ((const float4*)g)[threadIdx.x];
    float4 ov;
    ov.x = xv.x * sc * gv.x;
    ov.y = xv.y * sc * gv.y;
    ov.z = xv.z * sc * gv.z;
    ov.w = xv.w * sc * gv.w;
    ((float4*)(out + (size_t)row * DD))[threadIdx.x] = ov;
}

// ---------------------------------------------------------------------------
// SGEMM: C[M,N] = A[M,K] @ B[K,N] + bias[N] (+ ReLU) (+ residual[M,N])
// 128x128 block tile, BK=8, 256 threads, 8x8 per-thread micro-tile.
// EPI: 0 = bias only, 1 = bias + relu, 2 = bias + residual
// M,N,K all multiples of 128/8 here, so no bounds checks.
// ---------------------------------------------------------------------------
template<int EPI>
__global__ void __launch_bounds__(256) sgemm_kernel(
    const float* __restrict__ A, const float* __restrict__ Bm,
    const float* __restrict__ bias, const float* __restrict__ res,
    float* __restrict__ C, int Md, int Nd, int Kd)
{
    __shared__ float As[8][128];
    __shared__ float Bs[8][128];

    int tid  = threadIdx.x;
    int brow = blockIdx.y * 128;
    int bcol = blockIdx.x * 128;

    // A tile loaders: 128 rows x 8 cols, one float4 per thread
    int arow = tid >> 1;
    int acol = (tid & 1) * 4;
    // B tile loaders: 8 rows x 128 cols, one float4 per thread
    int bkr = tid >> 5;
    int bnc = (tid & 31) * 4;

    int tm = (tid >> 4) * 8;   // 0..120
    int tn = (tid & 15) * 8;   // 0..120

    float acc[8][8];
    #pragma unroll
    for (int i = 0; i < 8; i++)
        #pragma unroll
        for (int j = 0; j < 8; j++) acc[i][j] = 0.f;

    const float* Aptr = A + (size_t)(brow + arow) * Kd + acol;
    const float* Bptr = Bm + (size_t)bkr * Nd + bcol + bnc;

    for (int k0 = 0; k0 < Kd; k0 += 8) {
        float4 av = *(const float4*)(Aptr + k0);
        As[acol + 0][arow] = av.x;
        As[acol + 1][arow] = av.y;
        As[acol + 2][arow] = av.z;
        As[acol + 3][arow] = av.w;
        float4 bv = *(const float4*)(Bptr + (size_t)k0 * Nd);
        *(float4*)(&Bs[bkr][bnc]) = bv;
        __syncthreads();

        #pragma unroll
        for (int kk = 0; kk < 8; kk++) {
            float ra[8], rb[8];
            #pragma unroll
            for (int i = 0; i < 8; i++) ra[i] = As[kk][tm + i];
            #pragma unroll
            for (int j = 0; j < 8; j++) rb[j] = Bs[kk][tn + j];
            #pragma unroll
            for (int i = 0; i < 8; i++)
                #pragma unroll
                for (int j = 0; j < 8; j++)
                    acc[i][j] += ra[i] * rb[j];
        }
        __syncthreads();
    }

    // Epilogue
    #pragma unroll
    for (int i = 0; i < 8; i++) {
        int row = brow + tm + i;
        #pragma unroll
        for (int j = 0; j < 8; j += 4) {
            int col = bcol + tn + j;
            float4 b4 = *(const float4*)(bias + col);
            float4 o4;
            o4.x = acc[i][j + 0] + b4.x;
            o4.y = acc[i][j + 1] + b4.y;
            o4.z = acc[i][j + 2] + b4.z;
            o4.w = acc[i][j + 3] + b4.w;
            if (EPI == 1) {
                o4.x = fmaxf(o4.x, 0.f); o4.y = fmaxf(o4.y, 0.f);
                o4.z = fmaxf(o4.z, 0.f); o4.w = fmaxf(o4.w, 0.f);
            }
            if (EPI == 2) {
                float4 r4 = *(const float4*)(res + (size_t)row * Nd + col);
                o4.x += r4.x; o4.y += r4.y; o4.z += r4.z; o4.w += r4.w;
            }
            *(float4*)(C + (size_t)row * Nd + col) = o4;
        }
    }
}

// ---------------------------------------------------------------------------
// RoPE applied in-place to q and k. One thread per (row, head, freq-pair).
// q layout: [M, D] with head h occupying cols [h*64, h*64+64).
// pair (j, j+32): out[j] = x[j]*c - x[j+32]*s ; out[j+32] = x[j+32]*c + x[j]*s
// ---------------------------------------------------------------------------
__global__ void rope_kernel(float* __restrict__ q, float* __restrict__ k)
{
    int idx = blockIdx.x * blockDim.x + threadIdx.x;   // < MM*HH*32
    int j   = idx & 31;
    int h   = (idx >> 5) & (HH - 1);
    int row = idx >> 9;
    int s   = row & (SS - 1);   // row = b*SS + s

    float inv_freq = powf(10000.f, -(float)(2 * j) / (float)DKK);
    float ang = (float)s * inv_freq;
    float sn, cs;
    sincosf(ang, &sn, &cs);

    size_t base = (size_t)row * DD + h * DKK + j;

    float q1 = q[base], q2 = q[base + 32];
    q[base]      = q1 * cs - q2 * sn;
    q[base + 32] = q2 * cs + q1 * sn;

    float k1 = k[base], k2 = k[base + 32];
    k[base]      = k1 * cs - k2 * sn;
    k[base + 32] = k2 * cs + k1 * sn;
}

// ---------------------------------------------------------------------------
// Attention: flash-style. Grid (S/64, H, B), 64 threads (one query/thread).
// Online softmax, scores kept in registers in chunks of 16 keys.
// ---------------------------------------------------------------------------
__global__ void __launch_bounds__(64) attn_kernel(
    const float* __restrict__ q, const float* __restrict__ k,
    const float* __restrict__ v, float* __restrict__ o)
{
    __shared__ float Ks[64][64];
    __shared__ float Vs[64][64];

    int t  = threadIdx.x;
    int h  = blockIdx.y;
    int b  = blockIdx.z;
    int qi = blockIdx.x * 64 + t;

    size_t qoff = ((size_t)(b * SS + qi)) * DD + h * DKK;

    float qr[64];
    #pragma unroll
    for (int d = 0; d < 64; d += 4) {
        float4 qv = *(const float4*)(q + qoff + d);
        qr[d + 0] = qv.x * 0.125f;   // 1/sqrt(64)
        qr[d + 1] = qv.y * 0.125f;
        qr[d + 2] = qv.z * 0.125f;
        qr[d + 3] = qv.w * 0.125f;
    }

    float acc[64];
    #pragma unroll
    for (int d = 0; d < 64; d++) acc[d] = 0.f;
    float m = -1e30f, l = 0.f;

    size_t kvbase = ((size_t)(b * SS)) * DD + h * DKK;

    for (int kt = 0; kt < SS / 64; kt++) {
        __syncthreads();
        // cooperative tile load: 64 rows x 16 float4
        #pragma unroll
        for (int e = t; e < 64 * 16; e += 64) {
            int j  = e >> 4;
            int d4 = (e & 15) << 2;
            size_t src = kvbase + (size_t)(kt * 64 + j) * DD + d4;
            *(float4*)&Ks[j][d4] = *(const float4*)(k + src);
            *(float4*)&Vs[j][d4] = *(const float4*)(v + src);
        }
        __syncthreads();

        for (int jc = 0; jc < 64; jc += 16) {
            float sc[16];
            float cmax = -1e30f;
            #pragma unroll
            for (int jj = 0; jj < 16; jj++) {
                int j = jc + jj;
                float s0 = 0.f, s1 = 0.f, s2 = 0.f, s3 = 0.f;
                #pragma unroll
                for (int d = 0; d < 64; d += 4) {
                    s0 += qr[d + 0] * Ks[j][d + 0];
                    s1 += qr[d + 1] * Ks[j][d + 1];
                    s2 += qr[d + 2] * Ks[j][d + 2];
                    s3 += qr[d + 3] * Ks[j][d + 3];
                }
                sc[jj] = (s0 + s1) + (s2 + s3);
                cmax = fmaxf(cmax, sc[jj]);
            }
            float nm   = fmaxf(m, cmax);
            float corr = __expf(m - nm);
            l *= corr;
            #pragma unroll
            for (int d = 0; d < 64; d++) acc[d] *= corr;
            #pragma unroll
            for (int jj = 0; jj < 16; jj++) {
                float p = __expf(sc[jj] - nm);
                l += p;
                int j = jc + jj;
                #pragma unroll
                for (int d = 0; d < 64; d++) acc[d] += p * Vs[j][d];
            }
            m = nm;
        }
    }

    float invl = 1.f / l;
    #pragma unroll
    for (int d = 0; d < 64; d += 4) {
        float4 ov;
        ov.x = acc[d + 0] * invl;
        ov.y = acc[d + 1] * invl;
        ov.z = acc[d + 2] * invl;
        ov.w = acc[d + 3] * invl;
        *(float4*)(o + qoff + d) = ov;
    }
}

// ---------------------------------------------------------------------------
// Host orchestration
// ---------------------------------------------------------------------------
extern "C" void kernel_launch(void* const* d_in, const int* in_sizes, int n_in,
                              void* d_out, int out_size)
{
    (void)in_sizes; (void)n_in; (void)out_size;

    const float* x  = (const float*)d_in[0];
    const float* wq = (const float*)d_in[1];
    const float* bq = (const float*)d_in[2];
    const float* wk = (const float*)d_in[3];
    const float* bk = (const float*)d_in[4];
    const float* wv = (const float*)d_in[5];
    const float* bv = (const float*)d_in[6];
    const float* wo = (const float*)d_in[7];
    const float* bo = (const float*)d_in[8];
    const float* w1 = (const float*)d_in[9];
    const float* b1 = (const float*)d_in[10];
    const float* w2 = (const float*)d_in[11];
    const float* b2 = (const float*)d_in[12];
    const float* g1 = (const float*)d_in[13];
    const float* g2 = (const float*)d_in[14];
    float* out = (float*)d_out;

    float *ph, *pq, *pk, *pv, *po, *px2, *ph2, *pff;
    cudaGetSymbolAddress((void**)&ph,  g_h);
    cudaGetSymbolAddress((void**)&pq,  g_q);
    cudaGetSymbolAddress((void**)&pk,  g_k);
    cudaGetSymbolAddress((void**)&pv,  g_v);
    cudaGetSymbolAddress((void**)&po,  g_o);
    cudaGetSymbolAddress((void**)&px2, g_x2);
    cudaGetSymbolAddress((void**)&ph2, g_h2);
    cudaGetSymbolAddress((void**)&pff, g_ff);

    dim3 gD (DD  / 128, MM / 128);   // N=1024 GEMMs
    dim3 gF (DFFF/ 128, MM / 128);   // N=4096 GEMM

    // 1) h = rmsnorm(x, g1)
    rmsnorm_kernel<<<MM, 256>>>(x, g1, ph);

    // 2) q,k,v projections (+bias)
    sgemm_kernel<0><<<gD, 256>>>(ph, wq, bq, nullptr, pq, MM, DD, DD);
    sgemm_kernel<0><<<gD, 256>>>(ph, wk, bk, nullptr, pk, MM, DD, DD);
    sgemm_kernel<0><<<gD, 256>>>(ph, wv, bv, nullptr, pv, MM, DD, DD);

    // 3) RoPE on q,k
    rope_kernel<<<(MM * HH * 32) / 256, 256>>>(pq, pk);

    // 4) attention
    attn_kernel<<<dim3(SS / 64, HH, BB), 64>>>(pq, pk, pv, po);

    // 5) x2 = x + (o @ wo + bo)
    sgemm_kernel<2><<<gD, 256>>>(po, wo, bo, x, px2, MM, DD, DD);

    // 6) h2 = rmsnorm(x2, g2)
    rmsnorm_kernel<<<MM, 256>>>(px2, g2, ph2);

    // 7) ff = relu(h2 @ w1 + b1)
    sgemm_kernel<1><<<gF, 256>>>(ph2, w1, b1, nullptr, pff, MM, DFFF, DD);

    // 8) out = x2 + (ff @ w2 + b2)
    sgemm_kernel<2><<<gD, 256>>>(pff, w2, b2, px2, out, MM, DD, DFFF);
}

// round 3
// speedup vs baseline: 1.7944x; 1.7944x over previous
#include <cuda_runtime.h>
#include <cuda_bf16.h>
#include <cstdint>
#include <math.h>

// Problem constants
#define BB   2
#define SS   2048
#define DD   1024
#define HH   16
#define DKK  64
#define DFFF 4096
#define MM   (BB * SS)          // 4096 rows
#define EPSF 1.1920929e-07f

// ---------------------------------------------------------------------------
// Scratch (device globals — no cudaMalloc allowed)
// ---------------------------------------------------------------------------
__device__ float g_h  [MM * DD];
__device__ float g_q  [MM * DD];
__device__ float g_k  [MM * DD];
__device__ float g_v  [MM * DD];
__device__ float g_o  [MM * DD];
__device__ float g_x2 [MM * DD];
__device__ float g_h2 [MM * DD];
__device__ float g_ff [MM * DFFF];

// ---------------------------------------------------------------------------
// helpers
// ---------------------------------------------------------------------------
__device__ __forceinline__ uint32_t smem_u32(const void* p) {
    uint32_t a;
    asm("{ .reg .u64 t; cvta.to.shared.u64 t, %1; cvt.u32.u64 %0, t; }"
        : "=r"(a) : "l"(p));
    return a;
}
__device__ __forceinline__ void cp16(uint32_t saddr, const void* g) {
    asm volatile("cp.async.cg.shared.global [%0], [%1], 16;" :: "r"(saddr), "l"(g));
}
__device__ __forceinline__ uint32_t f2tf32(float f) {
    uint32_t r;
    asm("cvt.rna.tf32.f32 %0, %1;" : "=r"(r) : "f"(f));
    return r;
}
__device__ __forceinline__ void mma_tf32(
    float* c, const uint32_t* a, const uint32_t* b)
{
    asm volatile(
        "mma.sync.aligned.m16n8k8.row.col.f32.tf32.tf32.f32 "
        "{%0,%1,%2,%3}, {%4,%5,%6,%7}, {%8,%9}, {%0,%1,%2,%3};"
        : "+f"(c[0]), "+f"(c[1]), "+f"(c[2]), "+f"(c[3])
        : "r"(a[0]), "r"(a[1]), "r"(a[2]), "r"(a[3]), "r"(b[0]), "r"(b[1]));
}

// ---------------------------------------------------------------------------
// tf32 mma.sync GEMM: C[M,N] = A[M,K] @ B[K,N] + bias (+relu / +residual)
// CTA tile 128x128, BK=16, 256 threads (8 warps, 2x4 grid, 64x32 per warp).
// Double-buffered cp.async. A and B are plain row-major.
// EPI: 0 = bias, 1 = bias+relu, 2 = bias+residual
// ---------------------------------------------------------------------------
#define BM 128
#define BN 128
#define BK 16
#define APAD 20    // A smem row stride (floats)
#define BPAD 136   // B smem row stride (floats)

template<int EPI>
__global__ void __launch_bounds__(256, 1) gemm_mma(
    const float* __restrict__ A, const float* __restrict__ Bm,
    const float* __restrict__ bias, const float* __restrict__ res,
    float* __restrict__ C, int Md, int Nd, int Kd)
{
    __shared__ float As[2][BM][APAD];
    __shared__ float Bs[2][BK][BPAD];

    const int tid  = threadIdx.x;
    const int lane = tid & 31;
    const int wid  = tid >> 5;
    const int warp_m = (wid >> 2) * 64;
    const int warp_n = (wid & 3) * 32;
    const int brow = blockIdx.y * BM;
    const int bcol = blockIdx.x * BN;
    const int KT = Kd / BK;

    const int tg  = lane >> 2;   // groupID 0..7
    const int tig = lane & 3;    // threadInGroup 0..3

    float acc[4][4][4];
    #pragma unroll
    for (int i = 0; i < 4; i++)
        #pragma unroll
        for (int j = 0; j < 4; j++)
            #pragma unroll
            for (int r = 0; r < 4; r++) acc[i][j][r] = 0.f;

    // copy lambda replacement (macro-style inline)
    // A tile: 128 x 16 floats = 512 float4; B tile: 16 x 128 = 512 float4.
    #define COPY_STAGE(s, kt) do {                                             \
        int k0 = (kt) * BK;                                                    \
        _Pragma("unroll")                                                      \
        for (int i = 0; i < 2; i++) {                                          \
            int e = tid + i * 256;                                             \
            int m = e >> 2, c4 = (e & 3) << 2;                                 \
            cp16(smem_u32(&As[s][m][c4]),                                      \
                 A + (size_t)(brow + m) * Kd + k0 + c4);                       \
        }                                                                      \
        _Pragma("unroll")                                                      \
        for (int i = 0; i < 2; i++) {                                          \
            int e = tid + i * 256;                                             \
            int kr = e >> 5, c4 = (e & 31) << 2;                               \
            cp16(smem_u32(&Bs[s][kr][c4]),                                     \
                 Bm + (size_t)(k0 + kr) * Nd + bcol + c4);                     \
        }                                                                      \
        asm volatile("cp.async.commit_group;");                                \
    } while (0)

    COPY_STAGE(0, 0);

    for (int kt = 0; kt < KT; kt++) {
        int s = kt & 1;
        if (kt + 1 < KT) {
            COPY_STAGE(s ^ 1, kt + 1);
            asm volatile("cp.async.wait_group 1;");
        } else {
            asm volatile("cp.async.wait_group 0;");
        }
        __syncthreads();

        #pragma unroll
        for (int ks = 0; ks < 2; ks++) {
            int kc = ks * 8;
            uint32_t af[4][4], bf[4][2];
            #pragma unroll
            for (int mi = 0; mi < 4; mi++) {
                int rm = warp_m + mi * 16 + tg;
                af[mi][0] = f2tf32(As[s][rm    ][kc + tig]);
                af[mi][1] = f2tf32(As[s][rm + 8][kc + tig]);
                af[mi][2] = f2tf32(As[s][rm    ][kc + 4 + tig]);
                af[mi][3] = f2tf32(As[s][rm + 8][kc + 4 + tig]);
            }
            #pragma unroll
            for (int ni = 0; ni < 4; ni++) {
                int cn = warp_n + ni * 8 + tg;
                bf[ni][0] = f2tf32(Bs[s][kc + tig    ][cn]);
                bf[ni][1] = f2tf32(Bs[s][kc + 4 + tig][cn]);
            }
            #pragma unroll
            for (int mi = 0; mi < 4; mi++)
                #pragma unroll
                for (int ni = 0; ni < 4; ni++)
                    mma_tf32(acc[mi][ni], af[mi], bf[ni]);
        }
        __syncthreads();
    }

    // Epilogue
    #pragma unroll
    for (int mi = 0; mi < 4; mi++) {
        int row0 = brow + warp_m + mi * 16 + tg;
        #pragma unroll
        for (int ni = 0; ni < 4; ni++) {
            int col = bcol + warp_n + ni * 8 + tig * 2;
            float2 bv = *(const float2*)(bias + col);
            #pragma unroll
            for (int half = 0; half < 2; half++) {
                int row = row0 + half * 8;
                float v0 = acc[mi][ni][half * 2 + 0] + bv.x;
                float v1 = acc[mi][ni][half * 2 + 1] + bv.y;
                if (EPI == 1) { v0 = fmaxf(v0, 0.f); v1 = fmaxf(v1, 0.f); }
                if (EPI == 2) {
                    float2 rv = *(const float2*)(res + (size_t)row * Nd + col);
                    v0 += rv.x; v1 += rv.y;
                }
                float2 o2; o2.x = v0; o2.y = v1;
                *(float2*)(C + (size_t)row * Nd + col) = o2;
            }
        }
    }
    #undef COPY_STAGE
}

// ---------------------------------------------------------------------------
// RMSNorm
// ---------------------------------------------------------------------------
__global__ void __launch_bounds__(256) rmsnorm_kernel(
    const float* __restrict__ x, const float* __restrict__ g,
    float* __restrict__ out)
{
    int row = blockIdx.x;
    const float4* xr = (const float4*)(x + (size_t)row * DD);
    float4 xv = xr[threadIdx.x];
    float ss = xv.x * xv.x + xv.y * xv.y + xv.z * xv.z + xv.w * xv.w;
    #pragma unroll
    for (int off = 16; off > 0; off >>= 1)
        ss += __shfl_xor_sync(0xFFFFFFFFu, ss, off);
    __shared__ float sred[8];
    __shared__ float sscale;
    int warp = threadIdx.x >> 5;
    if ((threadIdx.x & 31) == 0) sred[warp] = ss;
    __syncthreads();
    if (threadIdx.x == 0) {
        float t = 0.f;
        #pragma unroll
        for (int i = 0; i < 8; i++) t += sred[i];
        sscale = rsqrtf(t / (float)DD + EPSF);
    }
    __syncthreads();
    float sc = sscale;
    float4 gv = ((const float4*)g)[threadIdx.x];
    float4 ov;
    ov.x = xv.x * sc * gv.x; ov.y = xv.y * sc * gv.y;
    ov.z = xv.z * sc * gv.z; ov.w = xv.w * sc * gv.w;
    ((float4*)(out + (size_t)row * DD))[threadIdx.x] = ov;
}

// ---------------------------------------------------------------------------
// RoPE
// ---------------------------------------------------------------------------
__global__ void rope_kernel(float* __restrict__ q, float* __restrict__ k)
{
    int idx = blockIdx.x * blockDim.x + threadIdx.x;
    int j   = idx & 31;
    int h   = (idx >> 5) & (HH - 1);
    int row = idx >> 9;
    int s   = row & (SS - 1);
    float inv_freq = powf(10000.f, -(float)(2 * j) / (float)DKK);
    float ang = (float)s * inv_freq;
    float sn, cs;
    sincosf(ang, &sn, &cs);
    size_t base = (size_t)row * DD + h * DKK + j;
    float q1 = q[base], q2 = q[base + 32];
    q[base]      = q1 * cs - q2 * sn;
    q[base + 32] = q2 * cs + q1 * sn;
    float k1 = k[base], k2 = k[base + 32];
    k[base]      = k1 * cs - k2 * sn;
    k[base + 32] = k2 * cs + k1 * sn;
}

// ---------------------------------------------------------------------------
// Attention (flash-style, fp32 — unchanged this round)
// ---------------------------------------------------------------------------
__global__ void __launch_bounds__(64) attn_kernel(
    const float* __restrict__ q, const float* __restrict__ k,
    const float* __restrict__ v, float* __restrict__ o)
{
    __shared__ float Ks[64][64];
    __shared__ float Vs[64][64];
    int t  = threadIdx.x;
    int h  = blockIdx.y;
    int b  = blockIdx.z;
    int qi = blockIdx.x * 64 + t;
    size_t qoff = ((size_t)(b * SS + qi)) * DD + h * DKK;

    float qr[64];
    #pragma unroll
    for (int d = 0; d < 64; d += 4) {
        float4 qv = *(const float4*)(q + qoff + d);
        qr[d + 0] = qv.x * 0.125f; qr[d + 1] = qv.y * 0.125f;
        qr[d + 2] = qv.z * 0.125f; qr[d + 3] = qv.w * 0.125f;
    }
    float acc[64];
    #pragma unroll
    for (int d = 0; d < 64; d++) acc[d] = 0.f;
    float m = -1e30f, l = 0.f;
    size_t kvbase = ((size_t)(b * SS)) * DD + h * DKK;

    for (int kt = 0; kt < SS / 64; kt++) {
        __syncthreads();
        #pragma unroll
        for (int e = t; e < 64 * 16; e += 64) {
            int j  = e >> 4;
            int d4 = (e & 15) << 2;
            size_t src = kvbase + (size_t)(kt * 64 + j) * DD + d4;
            *(float4*)&Ks[j][d4] = *(const float4*)(k + src);
            *(float4*)&Vs[j][d4] = *(const float4*)(v + src);
        }
        __syncthreads();
        for (int jc = 0; jc < 64; jc += 16) {
            float sc[16];
            float cmax = -1e30f;
            #pragma unroll
            for (int jj = 0; jj < 16; jj++) {
                int j = jc + jj;
                float s0 = 0.f, s1 = 0.f, s2 = 0.f, s3 = 0.f;
                #pragma unroll
                for (int d = 0; d < 64; d += 4) {
                    s0 += qr[d + 0] * Ks[j][d + 0];
                    s1 += qr[d + 1] * Ks[j][d + 1];
                    s2 += qr[d + 2] * Ks[j][d + 2];
                    s3 += qr[d + 3] * Ks[j][d + 3];
                }
                sc[jj] = (s0 + s1) + (s2 + s3);
                cmax = fmaxf(cmax, sc[jj]);
            }
            float nm   = fmaxf(m, cmax);
            float corr = __expf(m - nm);
            l *= corr;
            #pragma unroll
            for (int d = 0; d < 64; d++) acc[d] *= corr;
            #pragma unroll
            for (int jj = 0; jj < 16; jj++) {
                float p = __expf(sc[jj] - nm);
                l += p;
                int j = jc + jj;
                #pragma unroll
                for (int d = 0; d < 64; d++) acc[d] += p * Vs[j][d];
            }
            m = nm;
        }
    }
    float invl = 1.f / l;
    #pragma unroll
    for (int d = 0; d < 64; d += 4) {
        float4 ov;
        ov.x = acc[d + 0] * invl; ov.y = acc[d + 1] * invl;
        ov.z = acc[d + 2] * invl; ov.w = acc[d + 3] * invl;
        *(float4*)(o + qoff + d) = ov;
    }
}

// ---------------------------------------------------------------------------
// Host orchestration
// ---------------------------------------------------------------------------
extern "C" void kernel_launch(void* const* d_in, const int* in_sizes, int n_in,
                              void* d_out, int out_size)
{
    (void)in_sizes; (void)n_in; (void)out_size;

    const float* x  = (const float*)d_in[0];
    const float* wq = (const float*)d_in[1];
    const float* bq = (const float*)d_in[2];
    const float* wk = (const float*)d_in[3];
    const float* bk = (const float*)d_in[4];
    const float* wv = (const float*)d_in[5];
    const float* bv = (const float*)d_in[6];
    const float* wo = (const float*)d_in[7];
    const float* bo = (const float*)d_in[8];
    const float* w1 = (const float*)d_in[9];
    const float* b1 = (const float*)d_in[10];
    const float* w2 = (const float*)d_in[11];
    const float* b2 = (const float*)d_in[12];
    const float* g1 = (const float*)d_in[13];
    const float* g2 = (const float*)d_in[14];
    float* out = (float*)d_out;

    float *ph, *pq, *pk, *pv, *po, *px2, *ph2, *pff;
    cudaGetSymbolAddress((void**)&ph,  g_h);
    cudaGetSymbolAddress((void**)&pq,  g_q);
    cudaGetSymbolAddress((void**)&pk,  g_k);
    cudaGetSymbolAddress((void**)&pv,  g_v);
    cudaGetSymbolAddress((void**)&po,  g_o);
    cudaGetSymbolAddress((void**)&px2, g_x2);
    cudaGetSymbolAddress((void**)&ph2, g_h2);
    cudaGetSymbolAddress((void**)&pff, g_ff);

    dim3 gD(DD / BN,   MM / BM);   // (8, 32)
    dim3 gF(DFFF / BN, MM / BM);   // (32, 32)

    rmsnorm_kernel<<<MM, 256>>>(x, g1, ph);

    gemm_mma<0><<<gD, 256>>>(ph, wq, bq, nullptr, pq, MM, DD, DD);
    gemm_mma<0><<<gD, 256>>>(ph, wk, bk, nullptr, pk, MM, DD, DD);
    gemm_mma<0><<<gD, 256>>>(ph, wv, bv, nullptr, pv, MM, DD, DD);

    rope_kernel<<<(MM * HH * 32) / 256, 256>>>(pq, pk);

    attn_kernel<<<dim3(SS / 64, HH, BB), 64>>>(pq, pk, pv, po);

    gemm_mma<2><<<gD, 256>>>(po, wo, bo, x, px2, MM, DD, DD);

    rmsnorm_kernel<<<MM, 256>>>(px2, g2, ph2);

    gemm_mma<1><<<gF, 256>>>(ph2, w1, b1, nullptr, pff, MM, DFFF, DD);

    gemm_mma<2><<<gD, 256>>>(pff, w2, b2, px2, out, MM, DD, DFFF);
}

// round 4
// speedup vs baseline: 2.9336x; 1.6349x over previous
#include <cuda_runtime.h>
#include <cuda_bf16.h>
#include <cstdint>
#include <math.h>

// Problem constants
#define BB   2
#define SS   2048
#define DD   1024
#define HH   16
#define DKK  64
#define DFFF 4096
#define MM   (BB * SS)          // 4096 rows
#define EPSF 1.1920929e-07f

// ---------------------------------------------------------------------------
// Scratch (device globals — no cudaMalloc allowed)
// ---------------------------------------------------------------------------
__device__ float g_h  [MM * DD];
__device__ float g_q  [MM * DD];
__device__ float g_k  [MM * DD];
__device__ float g_v  [MM * DD];
__device__ float g_o  [MM * DD];
__device__ float g_x2 [MM * DD];
__device__ float g_h2 [MM * DD];
__device__ float g_ff [MM * DFFF];

// ---------------------------------------------------------------------------
// helpers
// ---------------------------------------------------------------------------
__device__ __forceinline__ uint32_t smem_u32(const void* p) {
    uint32_t a;
    asm("{ .reg .u64 t; cvta.to.shared.u64 t, %1; cvt.u32.u64 %0, t; }"
        : "=r"(a) : "l"(p));
    return a;
}
__device__ __forceinline__ void cp16(uint32_t saddr, const void* g) {
    asm volatile("cp.async.cg.shared.global [%0], [%1], 16;" :: "r"(saddr), "l"(g));
}
__device__ __forceinline__ uint32_t f2tf32(float f) {
    uint32_t r;
    asm("cvt.rna.tf32.f32 %0, %1;" : "=r"(r) : "f"(f));
    return r;
}
__device__ __forceinline__ void mma_tf32(
    float* c, const uint32_t* a, const uint32_t* b)
{
    asm volatile(
        "mma.sync.aligned.m16n8k8.row.col.f32.tf32.tf32.f32 "
        "{%0,%1,%2,%3}, {%4,%5,%6,%7}, {%8,%9}, {%0,%1,%2,%3};"
        : "+f"(c[0]), "+f"(c[1]), "+f"(c[2]), "+f"(c[3])
        : "r"(a[0]), "r"(a[1]), "r"(a[2]), "r"(a[3]), "r"(b[0]), "r"(b[1]));
}

// ---------------------------------------------------------------------------
// tf32 mma.sync GEMM (unchanged from R3 — proven)
// ---------------------------------------------------------------------------
#define BM 128
#define BN 128
#define BK 16
#define APAD 20
#define BPAD 136

template<int EPI>
__global__ void __launch_bounds__(256, 1) gemm_mma(
    const float* __restrict__ A, const float* __restrict__ Bm,
    const float* __restrict__ bias, const float* __restrict__ res,
    float* __restrict__ C, int Md, int Nd, int Kd)
{
    __shared__ float As[2][BM][APAD];
    __shared__ float Bs[2][BK][BPAD];

    const int tid  = threadIdx.x;
    const int lane = tid & 31;
    const int wid  = tid >> 5;
    const int warp_m = (wid >> 2) * 64;
    const int warp_n = (wid & 3) * 32;
    const int brow = blockIdx.y * BM;
    const int bcol = blockIdx.x * BN;
    const int KT = Kd / BK;

    const int tg  = lane >> 2;
    const int tig = lane & 3;

    float acc[4][4][4];
    #pragma unroll
    for (int i = 0; i < 4; i++)
        #pragma unroll
        for (int j = 0; j < 4; j++)
            #pragma unroll
            for (int r = 0; r < 4; r++) acc[i][j][r] = 0.f;

    #define COPY_STAGE(s, kt) do {                                             \
        int k0 = (kt) * BK;                                                    \
        _Pragma("unroll")                                                      \
        for (int i = 0; i < 2; i++) {                                          \
            int e = tid + i * 256;                                             \
            int m = e >> 2, c4 = (e & 3) << 2;                                 \
            cp16(smem_u32(&As[s][m][c4]),                                      \
                 A + (size_t)(brow + m) * Kd + k0 + c4);                       \
        }                                                                      \
        _Pragma("unroll")                                                      \
        for (int i = 0; i < 2; i++) {                                          \
            int e = tid + i * 256;                                             \
            int kr = e >> 5, c4 = (e & 31) << 2;                               \
            cp16(smem_u32(&Bs[s][kr][c4]),                                     \
                 Bm + (size_t)(k0 + kr) * Nd + bcol + c4);                     \
        }                                                                      \
        asm volatile("cp.async.commit_group;");                                \
    } while (0)

    COPY_STAGE(0, 0);

    for (int kt = 0; kt < KT; kt++) {
        int s = kt & 1;
        if (kt + 1 < KT) {
            COPY_STAGE(s ^ 1, kt + 1);
            asm volatile("cp.async.wait_group 1;");
        } else {
            asm volatile("cp.async.wait_group 0;");
        }
        __syncthreads();

        #pragma unroll
        for (int ks = 0; ks < 2; ks++) {
            int kc = ks * 8;
            uint32_t af[4][4], bf[4][2];
            #pragma unroll
            for (int mi = 0; mi < 4; mi++) {
                int rm = warp_m + mi * 16 + tg;
                af[mi][0] = f2tf32(As[s][rm    ][kc + tig]);
                af[mi][1] = f2tf32(As[s][rm + 8][kc + tig]);
                af[mi][2] = f2tf32(As[s][rm    ][kc + 4 + tig]);
                af[mi][3] = f2tf32(As[s][rm + 8][kc + 4 + tig]);
            }
            #pragma unroll
            for (int ni = 0; ni < 4; ni++) {
                int cn = warp_n + ni * 8 + tg;
                bf[ni][0] = f2tf32(Bs[s][kc + tig    ][cn]);
                bf[ni][1] = f2tf32(Bs[s][kc + 4 + tig][cn]);
            }
            #pragma unroll
            for (int mi = 0; mi < 4; mi++)
                #pragma unroll
                for (int ni = 0; ni < 4; ni++)
                    mma_tf32(acc[mi][ni], af[mi], bf[ni]);
        }
        __syncthreads();
    }

    #pragma unroll
    for (int mi = 0; mi < 4; mi++) {
        int row0 = brow + warp_m + mi * 16 + tg;
        #pragma unroll
        for (int ni = 0; ni < 4; ni++) {
            int col = bcol + warp_n + ni * 8 + tig * 2;
            float2 bv = *(const float2*)(bias + col);
            #pragma unroll
            for (int half = 0; half < 2; half++) {
                int row = row0 + half * 8;
                float v0 = acc[mi][ni][half * 2 + 0] + bv.x;
                float v1 = acc[mi][ni][half * 2 + 1] + bv.y;
                if (EPI == 1) { v0 = fmaxf(v0, 0.f); v1 = fmaxf(v1, 0.f); }
                if (EPI == 2) {
                    float2 rv = *(const float2*)(res + (size_t)row * Nd + col);
                    v0 += rv.x; v1 += rv.y;
                }
                float2 o2; o2.x = v0; o2.y = v1;
                *(float2*)(C + (size_t)row * Nd + col) = o2;
            }
        }
    }
    #undef COPY_STAGE
}

// ---------------------------------------------------------------------------
// RMSNorm
// ---------------------------------------------------------------------------
__global__ void __launch_bounds__(256) rmsnorm_kernel(
    const float* __restrict__ x, const float* __restrict__ g,
    float* __restrict__ out)
{
    int row = blockIdx.x;
    const float4* xr = (const float4*)(x + (size_t)row * DD);
    float4 xv = xr[threadIdx.x];
    float ss = xv.x * xv.x + xv.y * xv.y + xv.z * xv.z + xv.w * xv.w;
    #pragma unroll
    for (int off = 16; off > 0; off >>= 1)
        ss += __shfl_xor_sync(0xFFFFFFFFu, ss, off);
    __shared__ float sred[8];
    __shared__ float sscale;
    int warp = threadIdx.x >> 5;
    if ((threadIdx.x & 31) == 0) sred[warp] = ss;
    __syncthreads();
    if (threadIdx.x == 0) {
        float t = 0.f;
        #pragma unroll
        for (int i = 0; i < 8; i++) t += sred[i];
        sscale = rsqrtf(t / (float)DD + EPSF);
    }
    __syncthreads();
    float sc = sscale;
    float4 gv = ((const float4*)g)[threadIdx.x];
    float4 ov;
    ov.x = xv.x * sc * gv.x; ov.y = xv.y * sc * gv.y;
    ov.z = xv.z * sc * gv.z; ov.w = xv.w * sc * gv.w;
    ((float4*)(out + (size_t)row * DD))[threadIdx.x] = ov;
}

// ---------------------------------------------------------------------------
// RoPE
// ---------------------------------------------------------------------------
__global__ void rope_kernel(float* __restrict__ q, float* __restrict__ k)
{
    int idx = blockIdx.x * blockDim.x + threadIdx.x;
    int j   = idx & 31;
    int h   = (idx >> 5) & (HH - 1);
    int row = idx >> 9;
    int s   = row & (SS - 1);
    float inv_freq = powf(10000.f, -(float)(2 * j) / (float)DKK);
    float ang = (float)s * inv_freq;
    float sn, cs;
    sincosf(ang, &sn, &cs);
    size_t base = (size_t)row * DD + h * DKK + j;
    float q1 = q[base], q2 = q[base + 32];
    q[base]      = q1 * cs - q2 * sn;
    q[base + 32] = q2 * cs + q1 * sn;
    float k1 = k[base], k2 = k[base + 32];
    k[base]      = k1 * cs - k2 * sn;
    k[base + 32] = k2 * cs + k1 * sn;
}

// ---------------------------------------------------------------------------
// Flash attention with tf32 mma.sync.
// CTA: 64 queries x one (b,h). 4 warps x 16 query rows. 128 threads.
// K/V tiles 64x64 double-buffered via cp.async. P via smem round-trip.
// Smem strides: Ks/Ps = 68 floats, Vs = 72 floats (bank-conflict-free).
// ---------------------------------------------------------------------------
#define KSS 68
#define VSS 72
#define PSS 68
// float offsets within dynamic smem
#define OFF_K0 0
#define OFF_K1 (64 * KSS)
#define OFF_V0 (2 * 64 * KSS)
#define OFF_V1 (2 * 64 * KSS + 64 * VSS)
#define OFF_P  (2 * 64 * KSS + 2 * 64 * VSS)
#define ATTN_SMEM ((2 * 64 * KSS + 2 * 64 * VSS + 64 * PSS) * 4)

__global__ void __launch_bounds__(128, 1) attn_mma(
    const float* __restrict__ q, const float* __restrict__ k,
    const float* __restrict__ v, float* __restrict__ o)
{
    extern __shared__ float sm[];
    float* Ks[2] = { sm + OFF_K0, sm + OFF_K1 };
    float* Vs[2] = { sm + OFF_V0, sm + OFF_V1 };
    float* Ps    = sm + OFF_P;

    const int tid  = threadIdx.x;
    const int lane = tid & 31;
    const int wid  = tid >> 5;
    const int wm   = wid * 16;       // warp's query-row offset in CTA tile
    const int tg   = lane >> 2;
    const int tig  = lane & 3;

    const int h  = blockIdx.y;
    const int b  = blockIdx.z;
    const int q0 = blockIdx.x * 64;  // CTA query base within sequence
    const size_t hb = (size_t)h * DKK;

    // ---- Q fragments in registers (scaled by 1/sqrt(dk)=0.125, tf32) ----
    uint32_t qf[8][4];
    {
        size_t r0 = ((size_t)(b * SS + q0 + wm + tg)) * DD + hb;
        size_t r8 = r0 + (size_t)8 * DD;
        #pragma unroll
        for (int ks = 0; ks < 8; ks++) {
            int c = ks * 8 + tig;
            qf[ks][0] = f2tf32(q[r0 + c    ] * 0.125f);
            qf[ks][1] = f2tf32(q[r8 + c    ] * 0.125f);
            qf[ks][2] = f2tf32(q[r0 + c + 4] * 0.125f);
            qf[ks][3] = f2tf32(q[r8 + c + 4] * 0.125f);
        }
    }

    // ---- O accumulators + softmax state ----
    float oacc[8][4];
    #pragma unroll
    for (int ni = 0; ni < 8; ni++)
        #pragma unroll
        for (int r = 0; r < 4; r++) oacc[ni][r] = 0.f;
    float m0 = -1e30f, m1 = -1e30f, l0 = 0.f, l1 = 0.f;

    const size_t kvbase = ((size_t)(b * SS)) * DD + hb;

    // copy K/V tile kt into buffer bf: 8 iterations of (K cp16 + V cp16)
    #define KV_PREFETCH(bf, kt) do {                                          \
        const float* kg = k + kvbase + (size_t)((kt) * 64) * DD;              \
        const float* vg = v + kvbase + (size_t)((kt) * 64) * DD;              \
        uint32_t kb = smem_u32(Ks[bf]);                                       \
        uint32_t vb = smem_u32(Vs[bf]);                                       \
        _Pragma("unroll")                                                     \
        for (int i = 0; i < 8; i++) {                                         \
            int e = tid + i * 128;                                            \
            int row = e >> 4, c = e & 15;                                     \
            cp16(kb + row * (KSS * 4) + c * 16, kg + (size_t)row * DD + c * 4);\
            cp16(vb + row * (VSS * 4) + c * 16, vg + (size_t)row * DD + c * 4);\
        }                                                                     \
        asm volatile("cp.async.commit_group;");                               \
    } while (0)

    KV_PREFETCH(0, 0);

    const int NT = SS / 64;
    for (int kt = 0; kt < NT; kt++) {
        int cur = kt & 1;
        asm volatile("cp.async.wait_group 0;");
        __syncthreads();
        if (kt + 1 < NT) KV_PREFETCH(cur ^ 1, kt + 1);

        // ---- S = Q @ K^T : sacc[ni][4], 16 rows x 64 keys per warp ----
        float sacc[8][4];
        #pragma unroll
        for (int ni = 0; ni < 8; ni++)
            #pragma unroll
            for (int r = 0; r < 4; r++) sacc[ni][r] = 0.f;

        const float* Kc = Ks[cur];
        #pragma unroll
        for (int ks = 0; ks < 8; ks++) {
            int kc = ks * 8;
            #pragma unroll
            for (int ni = 0; ni < 8; ni++) {
                uint32_t bf2[2];
                int cn = ni * 8 + tg;               // key index
                bf2[0] = f2tf32(Kc[cn * KSS + kc + tig]);
                bf2[1] = f2tf32(Kc[cn * KSS + kc + 4 + tig]);
                mma_tf32(sacc[ni], qf[ks], bf2);
            }
        }

        // ---- online softmax ----
        float rmax0 = -1e30f, rmax1 = -1e30f;
        #pragma unroll
        for (int ni = 0; ni < 8; ni++) {
            rmax0 = fmaxf(rmax0, fmaxf(sacc[ni][0], sacc[ni][1]));
            rmax1 = fmaxf(rmax1, fmaxf(sacc[ni][2], sacc[ni][3]));
        }
        #pragma unroll
        for (int d = 1; d < 4; d <<= 1) {
            rmax0 = fmaxf(rmax0, __shfl_xor_sync(0xFFFFFFFFu, rmax0, d));
            rmax1 = fmaxf(rmax1, __shfl_xor_sync(0xFFFFFFFFu, rmax1, d));
        }
        float nm0 = fmaxf(m0, rmax0);
        float nm1 = fmaxf(m1, rmax1);
        float corr0 = __expf(m0 - nm0);
        float corr1 = __expf(m1 - nm1);

        float rsum0 = 0.f, rsum1 = 0.f;
        #pragma unroll
        for (int ni = 0; ni < 8; ni++) {
            float p0 = __expf(sacc[ni][0] - nm0);
            float p1 = __expf(sacc[ni][1] - nm0);
            float p2 = __expf(sacc[ni][2] - nm1);
            float p3 = __expf(sacc[ni][3] - nm1);
            rsum0 += p0 + p1;
            rsum1 += p2 + p3;
            // write P to smem (rows are warp-private)
            float* pr0 = Ps + (wm + tg) * PSS + ni * 8 + 2 * tig;
            float* pr1 = Ps + (wm + tg + 8) * PSS + ni * 8 + 2 * tig;
            pr0[0] = p0; pr0[1] = p1;
            pr1[0] = p2; pr1[1] = p3;
        }
        #pragma unroll
        for (int d = 1; d < 4; d <<= 1) {
            rsum0 += __shfl_xor_sync(0xFFFFFFFFu, rsum0, d);
            rsum1 += __shfl_xor_sync(0xFFFFFFFFu, rsum1, d);
        }
        l0 = l0 * corr0 + rsum0;
        l1 = l1 * corr1 + rsum1;
        m0 = nm0; m1 = nm1;

        #pragma unroll
        for (int ni = 0; ni < 8; ni++) {
            oacc[ni][0] *= corr0; oacc[ni][1] *= corr0;
            oacc[ni][2] *= corr1; oacc[ni][3] *= corr1;
        }

        __syncwarp();

        // ---- O += P @ V ----
        const float* Vc = Vs[cur];
        #pragma unroll
        for (int ks = 0; ks < 8; ks++) {
            int kc = ks * 8;
            uint32_t af[4];
            af[0] = f2tf32(Ps[(wm + tg    ) * PSS + kc + tig]);
            af[1] = f2tf32(Ps[(wm + tg + 8) * PSS + kc + tig]);
            af[2] = f2tf32(Ps[(wm + tg    ) * PSS + kc + 4 + tig]);
            af[3] = f2tf32(Ps[(wm + tg + 8) * PSS + kc + 4 + tig]);
            #pragma unroll
            for (int ni = 0; ni < 8; ni++) {
                uint32_t bf2[2];
                int cn = ni * 8 + tg;               // dk index
                bf2[0] = f2tf32(Vc[(kc + tig    ) * VSS + cn]);
                bf2[1] = f2tf32(Vc[(kc + 4 + tig) * VSS + cn]);
                mma_tf32(oacc[ni], af, bf2);
            }
        }
        __syncwarp();
    }

    // ---- finalize & store ----
    float inv0 = 1.f / l0;
    float inv1 = 1.f / l1;
    size_t r0 = ((size_t)(b * SS + q0 + wm + tg)) * DD + hb;
    size_t r8 = r0 + (size_t)8 * DD;
    #pragma unroll
    for (int ni = 0; ni < 8; ni++) {
        int c = ni * 8 + 2 * tig;
        float2 o0; o0.x = oacc[ni][0] * inv0; o0.y = oacc[ni][1] * inv0;
        float2 o1; o1.x = oacc[ni][2] * inv1; o1.y = oacc[ni][3] * inv1;
        *(float2*)(o + r0 + c) = o0;
        *(float2*)(o + r8 + c) = o1;
    }
    #undef KV_PREFETCH
}

// ---------------------------------------------------------------------------
// Host orchestration
// ---------------------------------------------------------------------------
extern "C" void kernel_launch(void* const* d_in, const int* in_sizes, int n_in,
                              void* d_out, int out_size)
{
    (void)in_sizes; (void)n_in; (void)out_size;

    const float* x  = (const float*)d_in[0];
    const float* wq = (const float*)d_in[1];
    const float* bq = (const float*)d_in[2];
    const float* wk = (const float*)d_in[3];
    const float* bk = (const float*)d_in[4];
    const float* wv = (const float*)d_in[5];
    const float* bv = (const float*)d_in[6];
    const float* wo = (const float*)d_in[7];
    const float* bo = (const float*)d_in[8];
    const float* w1 = (const float*)d_in[9];
    const float* b1 = (const float*)d_in[10];
    const float* w2 = (const float*)d_in[11];
    const float* b2 = (const float*)d_in[12];
    const float* g1 = (const float*)d_in[13];
    const float* g2 = (const float*)d_in[14];
    float* out = (float*)d_out;

    float *ph, *pq, *pk, *pv, *po, *px2, *ph2, *pff;
    cudaGetSymbolAddress((void**)&ph,  g_h);
    cudaGetSymbolAddress((void**)&pq,  g_q);
    cudaGetSymbolAddress((void**)&pk,  g_k);
    cudaGetSymbolAddress((void**)&pv,  g_v);
    cudaGetSymbolAddress((void**)&po,  g_o);
    cudaGetSymbolAddress((void**)&px2, g_x2);
    cudaGetSymbolAddress((void**)&ph2, g_h2);
    cudaGetSymbolAddress((void**)&pff, g_ff);

    cudaFuncSetAttribute(attn_mma,
        cudaFuncAttributeMaxDynamicSharedMemorySize, ATTN_SMEM);

    dim3 gD(DD / BN,   MM / BM);   // (8, 32)
    dim3 gF(DFFF / BN, MM / BM);   // (32, 32)

    rmsnorm_kernel<<<MM, 256>>>(x, g1, ph);

    gemm_mma<0><<<gD, 256>>>(ph, wq, bq, nullptr, pq, MM, DD, DD);
    gemm_mma<0><<<gD, 256>>>(ph, wk, bk, nullptr, pk, MM, DD, DD);
    gemm_mma<0><<<gD, 256>>>(ph, wv, bv, nullptr, pv, MM, DD, DD);

    rope_kernel<<<(MM * HH * 32) / 256, 256>>>(pq, pk);

    attn_mma<<<dim3(SS / 64, HH, BB), 128, ATTN_SMEM>>>(pq, pk, pv, po);

    gemm_mma<2><<<gD, 256>>>(po, wo, bo, x, px2, MM, DD, DD);

    rmsnorm_kernel<<<MM, 256>>>(px2, g2, ph2);

    gemm_mma<1><<<gF, 256>>>(ph2, w1, b1, nullptr, pff, MM, DFFF, DD);

    gemm_mma<2><<<gD, 256>>>(pff, w2, b2, px2, out, MM, DD, DFFF);
}

// round 5
// speedup vs baseline: 3.4499x; 1.1760x over previous
#include <cuda_runtime.h>
#include <cuda_bf16.h>
#include <cstdint>
#include <math.h>

// Problem constants
#define BB   2
#define SS   2048
#define DD   1024
#define HH   16
#define DKK  64
#define DFFF 4096
#define MM   (BB * SS)          // 4096 rows
#define EPSF 1.1920929e-07f

// ---------------------------------------------------------------------------
// Scratch (device globals — no cudaMalloc allowed)
// ---------------------------------------------------------------------------
__device__ float g_h  [MM * DD];
__device__ float g_q  [MM * DD];
__device__ float g_k  [MM * DD];
__device__ float g_v  [MM * DD];
__device__ float g_o  [MM * DD];
__device__ float g_x2 [MM * DD];
__device__ float g_h2 [MM * DD];
__device__ float g_ff [MM * DFFF];
// tf32-pre-rounded weights
__device__ float g_rwq[DD * DD];
__device__ float g_rwk[DD * DD];
__device__ float g_rwv[DD * DD];
__device__ float g_rwo[DD * DD];
__device__ float g_rw1[DD * DFFF];
__device__ float g_rw2[DFFF * DD];

// ---------------------------------------------------------------------------
// helpers
// ---------------------------------------------------------------------------
__device__ __forceinline__ uint32_t smem_u32(const void* p) {
    uint32_t a;
    asm("{ .reg .u64 t; cvta.to.shared.u64 t, %1; cvt.u32.u64 %0, t; }"
        : "=r"(a) : "l"(p));
    return a;
}
__device__ __forceinline__ void cp16(uint32_t saddr, const void* g) {
    asm volatile("cp.async.cg.shared.global [%0], [%1], 16;" :: "r"(saddr), "l"(g));
}
__device__ __forceinline__ uint32_t f2tf32(float f) {
    uint32_t r;
    asm("cvt.rna.tf32.f32 %0, %1;" : "=r"(r) : "f"(f));
    return r;
}
__device__ __forceinline__ float rtf(float f) {           // round-to-tf32 value
    return __uint_as_float(f2tf32(f));
}
__device__ __forceinline__ void mma_tf32(
    float* c, const uint32_t* a, const uint32_t* b)
{
    asm volatile(
        "mma.sync.aligned.m16n8k8.row.col.f32.tf32.tf32.f32 "
        "{%0,%1,%2,%3}, {%4,%5,%6,%7}, {%8,%9}, {%0,%1,%2,%3};"
        : "+f"(c[0]), "+f"(c[1]), "+f"(c[2]), "+f"(c[3])
        : "r"(a[0]), "r"(a[1]), "r"(a[2]), "r"(a[3]), "r"(b[0]), "r"(b[1]));
}

// ---------------------------------------------------------------------------
// tf32 rounding pass (for weights), float4-vectorized
// ---------------------------------------------------------------------------
__global__ void __launch_bounds__(256) round_tf32_kernel(
    const float* __restrict__ in, float* __restrict__ out)
{
    int i = blockIdx.x * 256 + threadIdx.x;
    float4 v = ((const float4*)in)[i];
    v.x = rtf(v.x); v.y = rtf(v.y); v.z = rtf(v.z); v.w = rtf(v.w);
    ((float4*)out)[i] = v;
}

// ---------------------------------------------------------------------------
// tf32 mma.sync GEMM. Inputs A and B must be tf32-pre-rounded.
// CTA tile 128x128, BK=16, 256 threads, 2x4 warps, double-buffered cp.async.
// EPI: 0 = bias, 1 = bias+relu, 2 = bias+residual. RND: round output to tf32.
// ---------------------------------------------------------------------------
#define BM 128
#define BN 128
#define BK 16
#define APAD 20
#define BPAD 136

template<int EPI, bool RND>
__global__ void __launch_bounds__(256, 2) gemm_mma(
    const float* __restrict__ A, const float* __restrict__ Bm,
    const float* __restrict__ bias, const float* __restrict__ res,
    float* __restrict__ C, int Md, int Nd, int Kd)
{
    __shared__ float As[2][BM][APAD];
    __shared__ float Bs[2][BK][BPAD];

    const int tid  = threadIdx.x;
    const int lane = tid & 31;
    const int wid  = tid >> 5;
    const int warp_m = (wid >> 2) * 64;
    const int warp_n = (wid & 3) * 32;
    const int brow = blockIdx.y * BM;
    const int bcol = blockIdx.x * BN;
    const int KT = Kd / BK;

    const int tg  = lane >> 2;
    const int tig = lane & 3;

    float acc[4][4][4];
    #pragma unroll
    for (int i = 0; i < 4; i++)
        #pragma unroll
        for (int j = 0; j < 4; j++)
            #pragma unroll
            for (int r = 0; r < 4; r++) acc[i][j][r] = 0.f;

    #define COPY_STAGE(s, kt) do {                                             \
        int k0 = (kt) * BK;                                                    \
        _Pragma("unroll")                                                      \
        for (int i = 0; i < 2; i++) {                                          \
            int e = tid + i * 256;                                             \
            int m = e >> 2, c4 = (e & 3) << 2;                                 \
            cp16(smem_u32(&As[s][m][c4]),                                      \
                 A + (size_t)(brow + m) * Kd + k0 + c4);                       \
        }                                                                      \
        _Pragma("unroll")                                                      \
        for (int i = 0; i < 2; i++) {                                          \
            int e = tid + i * 256;                                             \
            int kr = e >> 5, c4 = (e & 31) << 2;                               \
            cp16(smem_u32(&Bs[s][kr][c4]),                                     \
                 Bm + (size_t)(k0 + kr) * Nd + bcol + c4);                     \
        }                                                                      \
        asm volatile("cp.async.commit_group;");                                \
    } while (0)

    COPY_STAGE(0, 0);

    for (int kt = 0; kt < KT; kt++) {
        int s = kt & 1;
        if (kt + 1 < KT) {
            COPY_STAGE(s ^ 1, kt + 1);
            asm volatile("cp.async.wait_group 1;");
        } else {
            asm volatile("cp.async.wait_group 0;");
        }
        __syncthreads();

        #pragma unroll
        for (int ks = 0; ks < 2; ks++) {
            int kc = ks * 8;
            uint32_t af[4][4], bf[4][2];
            #pragma unroll
            for (int mi = 0; mi < 4; mi++) {
                int rm = warp_m + mi * 16 + tg;
                af[mi][0] = __float_as_uint(As[s][rm    ][kc + tig]);
                af[mi][1] = __float_as_uint(As[s][rm + 8][kc + tig]);
                af[mi][2] = __float_as_uint(As[s][rm    ][kc + 4 + tig]);
                af[mi][3] = __float_as_uint(As[s][rm + 8][kc + 4 + tig]);
            }
            #pragma unroll
            for (int ni = 0; ni < 4; ni++) {
                int cn = warp_n + ni * 8 + tg;
                bf[ni][0] = __float_as_uint(Bs[s][kc + tig    ][cn]);
                bf[ni][1] = __float_as_uint(Bs[s][kc + 4 + tig][cn]);
            }
            #pragma unroll
            for (int mi = 0; mi < 4; mi++)
                #pragma unroll
                for (int ni = 0; ni < 4; ni++)
                    mma_tf32(acc[mi][ni], af[mi], bf[ni]);
        }
        __syncthreads();
    }

    #pragma unroll
    for (int mi = 0; mi < 4; mi++) {
        int row0 = brow + warp_m + mi * 16 + tg;
        #pragma unroll
        for (int ni = 0; ni < 4; ni++) {
            int col = bcol + warp_n + ni * 8 + tig * 2;
            float2 bv = *(const float2*)(bias + col);
            #pragma unroll
            for (int half = 0; half < 2; half++) {
                int row = row0 + half * 8;
                float v0 = acc[mi][ni][half * 2 + 0] + bv.x;
                float v1 = acc[mi][ni][half * 2 + 1] + bv.y;
                if (EPI == 1) { v0 = fmaxf(v0, 0.f); v1 = fmaxf(v1, 0.f); }
                if (EPI == 2) {
                    float2 rv = *(const float2*)(res + (size_t)row * Nd + col);
                    v0 += rv.x; v1 += rv.y;
                }
                if (RND) { v0 = rtf(v0); v1 = rtf(v1); }
                float2 o2; o2.x = v0; o2.y = v1;
                *(float2*)(C + (size_t)row * Nd + col) = o2;
            }
        }
    }
    #undef COPY_STAGE
}

// ---------------------------------------------------------------------------
// RMSNorm (outputs tf32-rounded — consumed only by GEMMs)
// ---------------------------------------------------------------------------
__global__ void __launch_bounds__(256) rmsnorm_kernel(
    const float* __restrict__ x, const float* __restrict__ g,
    float* __restrict__ out)
{
    int row = blockIdx.x;
    const float4* xr = (const float4*)(x + (size_t)row * DD);
    float4 xv = xr[threadIdx.x];
    float ss = xv.x * xv.x + xv.y * xv.y + xv.z * xv.z + xv.w * xv.w;
    #pragma unroll
    for (int off = 16; off > 0; off >>= 1)
        ss += __shfl_xor_sync(0xFFFFFFFFu, ss, off);
    __shared__ float sred[8];
    __shared__ float sscale;
    int warp = threadIdx.x >> 5;
    if ((threadIdx.x & 31) == 0) sred[warp] = ss;
    __syncthreads();
    if (threadIdx.x == 0) {
        float t = 0.f;
        #pragma unroll
        for (int i = 0; i < 8; i++) t += sred[i];
        sscale = rsqrtf(t / (float)DD + EPSF);
    }
    __syncthreads();
    float sc = sscale;
    float4 gv = ((const float4*)g)[threadIdx.x];
    float4 ov;
    ov.x = rtf(xv.x * sc * gv.x); ov.y = rtf(xv.y * sc * gv.y);
    ov.z = rtf(xv.z * sc * gv.z); ov.w = rtf(xv.w * sc * gv.w);
    ((float4*)(out + (size_t)row * DD))[threadIdx.x] = ov;
}

// ---------------------------------------------------------------------------
// RoPE (outputs tf32-rounded — consumed only by attention MMAs)
// ---------------------------------------------------------------------------
__global__ void rope_kernel(float* __restrict__ q, float* __restrict__ k)
{
    int idx = blockIdx.x * blockDim.x + threadIdx.x;
    int j   = idx & 31;
    int h   = (idx >> 5) & (HH - 1);
    int row = idx >> 9;
    int s   = row & (SS - 1);
    float inv_freq = powf(10000.f, -(float)(2 * j) / (float)DKK);
    float ang = (float)s * inv_freq;
    float sn, cs;
    sincosf(ang, &sn, &cs);
    size_t base = (size_t)row * DD + h * DKK + j;
    float q1 = q[base], q2 = q[base + 32];
    q[base]      = rtf(q1 * cs - q2 * sn);
    q[base + 32] = rtf(q2 * cs + q1 * sn);
    float k1 = k[base], k2 = k[base + 32];
    k[base]      = rtf(k1 * cs - k2 * sn);
    k[base + 32] = rtf(k2 * cs + k1 * sn);
}

// ---------------------------------------------------------------------------
// Flash attention with tf32 mma.sync. Q/K/V pre-rounded by producers.
// CTA: 64 queries x one (b,h). 4 warps. K/V 64x64 double-buffered cp.async.
// ---------------------------------------------------------------------------
#define KSS 68
#define VSS 72
#define PSS 68
#define OFF_K0 0
#define OFF_K1 (64 * KSS)
#define OFF_V0 (2 * 64 * KSS)
#define OFF_V1 (2 * 64 * KSS + 64 * VSS)
#define OFF_P  (2 * 64 * KSS + 2 * 64 * VSS)
#define ATTN_SMEM ((2 * 64 * KSS + 2 * 64 * VSS + 64 * PSS) * 4)

__global__ void __launch_bounds__(128, 2) attn_mma(
    const float* __restrict__ q, const float* __restrict__ k,
    const float* __restrict__ v, float* __restrict__ o)
{
    extern __shared__ float sm[];
    float* Ks[2] = { sm + OFF_K0, sm + OFF_K1 };
    float* Vs[2] = { sm + OFF_V0, sm + OFF_V1 };
    float* Ps    = sm + OFF_P;

    const int tid  = threadIdx.x;
    const int lane = tid & 31;
    const int wid  = tid >> 5;
    const int wm   = wid * 16;
    const int tg   = lane >> 2;
    const int tig  = lane & 3;

    const int h  = blockIdx.y;
    const int b  = blockIdx.z;
    const int q0 = blockIdx.x * 64;
    const size_t hb = (size_t)h * DKK;

    // Q fragments: pre-rounded; *0.125f is exact (power of two)
    uint32_t qf[8][4];
    {
        size_t r0 = ((size_t)(b * SS + q0 + wm + tg)) * DD + hb;
        size_t r8 = r0 + (size_t)8 * DD;
        #pragma unroll
        for (int ks = 0; ks < 8; ks++) {
            int c = ks * 8 + tig;
            qf[ks][0] = __float_as_uint(q[r0 + c    ] * 0.125f);
            qf[ks][1] = __float_as_uint(q[r8 + c    ] * 0.125f);
            qf[ks][2] = __float_as_uint(q[r0 + c + 4] * 0.125f);
            qf[ks][3] = __float_as_uint(q[r8 + c + 4] * 0.125f);
        }
    }

    float oacc[8][4];
    #pragma unroll
    for (int ni = 0; ni < 8; ni++)
        #pragma unroll
        for (int r = 0; r < 4; r++) oacc[ni][r] = 0.f;
    float m0 = -1e30f, m1 = -1e30f, l0 = 0.f, l1 = 0.f;

    const size_t kvbase = ((size_t)(b * SS)) * DD + hb;

    #define KV_PREFETCH(bf, kt) do {                                          \
        const float* kg = k + kvbase + (size_t)((kt) * 64) * DD;              \
        const float* vg = v + kvbase + (size_t)((kt) * 64) * DD;              \
        uint32_t kb = smem_u32(Ks[bf]);                                       \
        uint32_t vb = smem_u32(Vs[bf]);                                       \
        _Pragma("unroll")                                                     \
        for (int i = 0; i < 8; i++) {                                         \
            int e = tid + i * 128;                                            \
            int row = e >> 4, c = e & 15;                                     \
            cp16(kb + row * (KSS * 4) + c * 16, kg + (size_t)row * DD + c * 4);\
            cp16(vb + row * (VSS * 4) + c * 16, vg + (size_t)row * DD + c * 4);\
        }                                                                     \
        asm volatile("cp.async.commit_group;");                               \
    } while (0)

    KV_PREFETCH(0, 0);

    const int NT = SS / 64;
    for (int kt = 0; kt < NT; kt++) {
        int cur = kt & 1;
        asm volatile("cp.async.wait_group 0;");
        __syncthreads();
        if (kt + 1 < NT) KV_PREFETCH(cur ^ 1, kt + 1);

        // S = Q @ K^T
        float sacc[8][4];
        #pragma unroll
        for (int ni = 0; ni < 8; ni++)
            #pragma unroll
            for (int r = 0; r < 4; r++) sacc[ni][r] = 0.f;

        const float* Kc = Ks[cur];
        #pragma unroll
        for (int ks = 0; ks < 8; ks++) {
            int kc = ks * 8;
            #pragma unroll
            for (int ni = 0; ni < 8; ni++) {
                uint32_t bf2[2];
                int cn = ni * 8 + tg;
                bf2[0] = __float_as_uint(Kc[cn * KSS + kc + tig]);
                bf2[1] = __float_as_uint(Kc[cn * KSS + kc + 4 + tig]);
                mma_tf32(sacc[ni], qf[ks], bf2);
            }
        }

        // online softmax
        float rmax0 = -1e30f, rmax1 = -1e30f;
        #pragma unroll
        for (int ni = 0; ni < 8; ni++) {
            rmax0 = fmaxf(rmax0, fmaxf(sacc[ni][0], sacc[ni][1]));
            rmax1 = fmaxf(rmax1, fmaxf(sacc[ni][2], sacc[ni][3]));
        }
        #pragma unroll
        for (int d = 1; d < 4; d <<= 1) {
            rmax0 = fmaxf(rmax0, __shfl_xor_sync(0xFFFFFFFFu, rmax0, d));
            rmax1 = fmaxf(rmax1, __shfl_xor_sync(0xFFFFFFFFu, rmax1, d));
        }
        float nm0 = fmaxf(m0, rmax0);
        float nm1 = fmaxf(m1, rmax1);
        float corr0 = __expf(m0 - nm0);
        float corr1 = __expf(m1 - nm1);

        float rsum0 = 0.f, rsum1 = 0.f;
        #pragma unroll
        for (int ni = 0; ni < 8; ni++) {
            float p0 = __expf(sacc[ni][0] - nm0);
            float p1 = __expf(sacc[ni][1] - nm0);
            float p2 = __expf(sacc[ni][2] - nm1);
            float p3 = __expf(sacc[ni][3] - nm1);
            rsum0 += p0 + p1;
            rsum1 += p2 + p3;
            float* pr0 = Ps + (wm + tg) * PSS + ni * 8 + 2 * tig;
            float* pr1 = Ps + (wm + tg + 8) * PSS + ni * 8 + 2 * tig;
            pr0[0] = p0; pr0[1] = p1;
            pr1[0] = p2; pr1[1] = p3;
        }
        #pragma unroll
        for (int d = 1; d < 4; d <<= 1) {
            rsum0 += __shfl_xor_sync(0xFFFFFFFFu, rsum0, d);
            rsum1 += __shfl_xor_sync(0xFFFFFFFFu, rsum1, d);
        }
        l0 = l0 * corr0 + rsum0;
        l1 = l1 * corr1 + rsum1;
        m0 = nm0; m1 = nm1;

        #pragma unroll
        for (int ni = 0; ni < 8; ni++) {
            oacc[ni][0] *= corr0; oacc[ni][1] *= corr0;
            oacc[ni][2] *= corr1; oacc[ni][3] *= corr1;
        }

        __syncwarp();

        // O += P @ V
        const float* Vc = Vs[cur];
        #pragma unroll
        for (int ks = 0; ks < 8; ks++) {
            int kc = ks * 8;
            uint32_t af[4];
            af[0] = f2tf32(Ps[(wm + tg    ) * PSS + kc + tig]);
            af[1] = f2tf32(Ps[(wm + tg + 8) * PSS + kc + tig]);
            af[2] = f2tf32(Ps[(wm + tg    ) * PSS + kc + 4 + tig]);
            af[3] = f2tf32(Ps[(wm + tg + 8) * PSS + kc + 4 + tig]);
            #pragma unroll
            for (int ni = 0; ni < 8; ni++) {
                uint32_t bf2[2];
                int cn = ni * 8 + tg;
                bf2[0] = __float_as_uint(Vc[(kc + tig    ) * VSS + cn]);
                bf2[1] = __float_as_uint(Vc[(kc + 4 + tig) * VSS + cn]);
                mma_tf32(oacc[ni], af, bf2);
            }
        }
        __syncwarp();
    }

    // finalize, round for the wo GEMM
    float inv0 = 1.f / l0;
    float inv1 = 1.f / l1;
    size_t r0 = ((size_t)(b * SS + q0 + wm + tg)) * DD + hb;
    size_t r8 = r0 + (size_t)8 * DD;
    #pragma unroll
    for (int ni = 0; ni < 8; ni++) {
        int c = ni * 8 + 2 * tig;
        float2 o0; o0.x = rtf(oacc[ni][0] * inv0); o0.y = rtf(oacc[ni][1] * inv0);
        float2 o1; o1.x = rtf(oacc[ni][2] * inv1); o1.y = rtf(oacc[ni][3] * inv1);
        *(float2*)(o + r0 + c) = o0;
        *(float2*)(o + r8 + c) = o1;
    }
    #undef KV_PREFETCH
}

// ---------------------------------------------------------------------------
// Host orchestration
// ---------------------------------------------------------------------------
extern "C" void kernel_launch(void* const* d_in, const int* in_sizes, int n_in,
                              void* d_out, int out_size)
{
    (void)in_sizes; (void)n_in; (void)out_size;

    const float* x  = (const float*)d_in[0];
    const float* wq = (const float*)d_in[1];
    const float* bq = (const float*)d_in[2];
    const float* wk = (const float*)d_in[3];
    const float* bk = (const float*)d_in[4];
    const float* wv = (const float*)d_in[5];
    const float* bv = (const float*)d_in[6];
    const float* wo = (const float*)d_in[7];
    const float* bo = (const float*)d_in[8];
    const float* w1 = (const float*)d_in[9];
    const float* b1 = (const float*)d_in[10];
    const float* w2 = (const float*)d_in[11];
    const float* b2 = (const float*)d_in[12];
    const float* g1 = (const float*)d_in[13];
    const float* g2 = (const float*)d_in[14];
    float* out = (float*)d_out;

    float *ph, *pq, *pk, *pv, *po, *px2, *ph2, *pff;
    float *prwq, *prwk, *prwv, *prwo, *prw1, *prw2;
    cudaGetSymbolAddress((void**)&ph,  g_h);
    cudaGetSymbolAddress((void**)&pq,  g_q);
    cudaGetSymbolAddress((void**)&pk,  g_k);
    cudaGetSymbolAddress((void**)&pv,  g_v);
    cudaGetSymbolAddress((void**)&po,  g_o);
    cudaGetSymbolAddress((void**)&px2, g_x2);
    cudaGetSymbolAddress((void**)&ph2, g_h2);
    cudaGetSymbolAddress((void**)&pff, g_ff);
    cudaGetSymbolAddress((void**)&prwq, g_rwq);
    cudaGetSymbolAddress((void**)&prwk, g_rwk);
    cudaGetSymbolAddress((void**)&prwv, g_rwv);
    cudaGetSymbolAddress((void**)&prwo, g_rwo);
    cudaGetSymbolAddress((void**)&prw1, g_rw1);
    cudaGetSymbolAddress((void**)&prw2, g_rw2);

    cudaFuncSetAttribute(attn_mma,
        cudaFuncAttributeMaxDynamicSharedMemorySize, ATTN_SMEM);

    dim3 gD(DD / BN,   MM / BM);   // (8, 32)
    dim3 gF(DFFF / BN, MM / BM);   // (32, 32)

    // Pre-round weights to tf32 (independent of activations; run first)
    round_tf32_kernel<<<(DD * DD) / 1024, 256>>>(wq, prwq);
    round_tf32_kernel<<<(DD * DD) / 1024, 256>>>(wk, prwk);
    round_tf32_kernel<<<(DD * DD) / 1024, 256>>>(wv, prwv);
    round_tf32_kernel<<<(DD * DD) / 1024, 256>>>(wo, prwo);
    round_tf32_kernel<<<(DD * DFFF) / 1024, 256>>>(w1, prw1);
    round_tf32_kernel<<<(DFFF * DD) / 1024, 256>>>(w2, prw2);

    rmsnorm_kernel<<<MM, 256>>>(x, g1, ph);

    gemm_mma<0, false><<<gD, 256>>>(ph, prwq, bq, nullptr, pq, MM, DD, DD);
    gemm_mma<0, false><<<gD, 256>>>(ph, prwk, bk, nullptr, pk, MM, DD, DD);
    gemm_mma<0, true ><<<gD, 256>>>(ph, prwv, bv, nullptr, pv, MM, DD, DD);

    rope_kernel<<<(MM * HH * 32) / 256, 256>>>(pq, pk);

    attn_mma<<<dim3(SS / 64, HH, BB), 128, ATTN_SMEM>>>(pq, pk, pv, po);

    gemm_mma<2, false><<<gD, 256>>>(po, prwo, bo, x, px2, MM, DD, DD);

    rmsnorm_kernel<<<MM, 256>>>(px2, g2, ph2);

    gemm_mma<1, true ><<<gF, 256>>>(ph2, prw1, b1, nullptr, pff, MM, DFFF, DD);

    gemm_mma<2, false><<<gD, 256>>>(pff, prw2, b2, px2, out, MM, DD, DFFF);
}